// round 2
// baseline (speedup 1.0000x reference)
#include <cuda_runtime.h>

#define NB 262144
#define NTHREADS (NB / 2)   // 2 elements per thread via f32x2
#define BLOCK 256

typedef unsigned long long u64;

__device__ __forceinline__ u64 pack2(float lo, float hi) {
    u64 r; asm("mov.b64 %0, {%1,%2};" : "=l"(r) : "f"(lo), "f"(hi)); return r;
}
__device__ __forceinline__ void unpack2(u64 v, float& lo, float& hi) {
    asm("mov.b64 {%0,%1}, %2;" : "=f"(lo), "=f"(hi) : "l"(v));
}
__device__ __forceinline__ u64 fma2(u64 a, u64 b, u64 c) {
    u64 r; asm("fma.rn.f32x2 %0, %1, %2, %3;" : "=l"(r) : "l"(a), "l"(b), "l"(c)); return r;
}
__device__ __forceinline__ u64 relu2(u64 x) {
    float lo, hi; unpack2(x, lo, hi);
    lo = fmaxf(lo, 0.0f); hi = fmaxf(hi, 0.0f);
    return pack2(lo, hi);
}

__global__ __launch_bounds__(BLOCK)
void hybridq_kernel(const float* __restrict__ xq, const float* __restrict__ xc,
                    const float* __restrict__ qp,
                    const float* __restrict__ W1, const float* __restrict__ b1,
                    const float* __restrict__ W2, const float* __restrict__ b2,
                    const float* __restrict__ W3, const float* __restrict__ b3,
                    float* __restrict__ out)
{
    // Transposed, f32x2-duplicated weights in SMEM. Row pads keep 16B alignment
    // so the inner loops compile to LDS.128 (ulonglong2).
    __shared__ u64 sW1[32][18];   // [out][in], 17 used, pad to 18 (144B rows)
    __shared__ u64 sW2[16][32];   // [out][in]
    __shared__ u64 sW3[16];
    __shared__ u64 sb1[32];
    __shared__ u64 sb2[16];

    const int tid = threadIdx.x;
    for (int i = tid; i < 32 * 17; i += BLOCK) {
        int j = i / 17, k = i % 17;
        float w = W1[k * 32 + j];
        sW1[j][k] = pack2(w, w);
    }
    for (int i = tid; i < 16 * 32; i += BLOCK) {
        int j = i / 32, k = i % 32;
        float w = W2[k * 16 + j];
        sW2[j][k] = pack2(w, w);
    }
    if (tid < 32) { float v = b1[tid]; sb1[tid] = pack2(v, v); }
    if (tid < 16) {
        float w = W3[tid]; sW3[tid] = pack2(w, w);
        float v = b2[tid]; sb2[tid] = pack2(v, v);
    }
    __syncthreads();

    const int t  = blockIdx.x * BLOCK + tid;
    const int e0 = t;
    const int e1 = t + NTHREADS;

    // ---- Quantum feature: <Z0> = prod_{i=1..6} cos(x_q[i] + qp[i]) ----
    // CNOT-ring GF(2) algebra: final qubit-0 value = parity(b1..b6), so
    // qubit 0's own angle cancels and each factor is cos^2(h)-sin^2(h)=cos(2h)=cos(x+w).
    float qv0 = 1.0f, qv1 = 1.0f;
#pragma unroll
    for (int i = 1; i < 7; i++) {
        float w = __ldg(qp + i);
        qv0 *= __cosf(__ldg(xq + e0 * 7 + i) + w);
        qv1 *= __cosf(__ldg(xq + e1 * 7 + i) + w);
    }

    // ---- Pack inputs: feature 0 = q_out, features 1..16 = x_c ----
    u64 in[17];
    in[0] = pack2(qv0, qv1);
    const float4* c0 = (const float4*)(xc + (long)e0 * 16);
    const float4* c1 = (const float4*)(xc + (long)e1 * 16);
#pragma unroll
    for (int q = 0; q < 4; q++) {
        float4 a = __ldg(c0 + q);
        float4 b = __ldg(c1 + q);
        in[1 + q * 4 + 0] = pack2(a.x, b.x);
        in[1 + q * 4 + 1] = pack2(a.y, b.y);
        in[1 + q * 4 + 2] = pack2(a.z, b.z);
        in[1 + q * 4 + 3] = pack2(a.w, b.w);
    }

    // ---- Layer 1: 17 -> 32, relu ----
    u64 h1[32];
#pragma unroll
    for (int j = 0; j < 32; j++) {
        u64 acc = sb1[j];
        const ulonglong2* row = (const ulonglong2*)&sW1[j][0];
#pragma unroll
        for (int kk = 0; kk < 8; kk++) {
            ulonglong2 w = row[kk];
            acc = fma2(in[2 * kk + 0], w.x, acc);
            acc = fma2(in[2 * kk + 1], w.y, acc);
        }
        acc = fma2(in[16], sW1[j][16], acc);
        h1[j] = relu2(acc);
    }

    // ---- Layer 2: 32 -> 16, relu ----
    u64 h2[16];
#pragma unroll
    for (int j = 0; j < 16; j++) {
        u64 acc = sb2[j];
        const ulonglong2* row = (const ulonglong2*)&sW2[j][0];
#pragma unroll
        for (int kk = 0; kk < 16; kk++) {
            ulonglong2 w = row[kk];
            acc = fma2(h1[2 * kk + 0], w.x, acc);
            acc = fma2(h1[2 * kk + 1], w.y, acc);
        }
        h2[j] = relu2(acc);
    }

    // ---- Layer 3: 16 -> 1 ----
    float bb = __ldg(b3);
    u64 acc = pack2(bb, bb);
#pragma unroll
    for (int k = 0; k < 16; k++)
        acc = fma2(h2[k], sW3[k], acc);

    float o0, o1;
    unpack2(acc, o0, o1);
    out[e0] = o0;
    out[e1] = o1;
}

extern "C" void kernel_launch(void* const* d_in, const int* in_sizes, int n_in,
                              void* d_out, int out_size)
{
    const float* xq = (const float*)d_in[0];
    const float* xc = (const float*)d_in[1];
    const float* qp = (const float*)d_in[2];
    const float* W1 = (const float*)d_in[3];
    const float* b1 = (const float*)d_in[4];
    const float* W2 = (const float*)d_in[5];
    const float* b2 = (const float*)d_in[6];
    const float* W3 = (const float*)d_in[7];
    const float* b3 = (const float*)d_in[8];
    float* out = (float*)d_out;

    hybridq_kernel<<<NTHREADS / BLOCK, BLOCK>>>(xq, xc, qp, W1, b1, W2, b2, W3, b3, out);
}

// round 3
// speedup vs baseline: 1.2481x; 1.2481x over previous
#include <cuda_runtime.h>

#define NB 262144
#define EPT 4
#define NTHREADS (NB / EPT)   // 65536 threads, 4 elements each (2x f32x2)
#define BLOCK 128

typedef unsigned long long u64;

__device__ __forceinline__ u64 pack2(float lo, float hi) {
    u64 r; asm("mov.b64 %0, {%1,%2};" : "=l"(r) : "f"(lo), "f"(hi)); return r;
}
__device__ __forceinline__ void unpack2(u64 v, float& lo, float& hi) {
    asm("mov.b64 {%0,%1}, %2;" : "=f"(lo), "=f"(hi) : "l"(v));
}
__device__ __forceinline__ u64 fma2(u64 a, u64 b, u64 c) {
    u64 r; asm("fma.rn.f32x2 %0, %1, %2, %3;" : "=l"(r) : "l"(a), "l"(b), "l"(c)); return r;
}
__device__ __forceinline__ u64 relu2(u64 x) {
    float lo, hi; unpack2(x, lo, hi);
    lo = fmaxf(lo, 0.0f); hi = fmaxf(hi, 0.0f);
    return pack2(lo, hi);
}

__global__ __launch_bounds__(BLOCK, 3)
void hybridq_kernel(const float* __restrict__ xq, const float* __restrict__ xc,
                    const float* __restrict__ qp,
                    const float* __restrict__ W1, const float* __restrict__ b1,
                    const float* __restrict__ W2, const float* __restrict__ b2,
                    const float* __restrict__ W3, const float* __restrict__ b3,
                    float* __restrict__ out)
{
    // Duplicated-f32x2 weights in SMEM.
    // sW1: [out k][in i], rows padded to 18 u64 (144B, 16B-aligned).
    // sW2: [k][j] — W2's native row-major layout, so layer-2 accumulation
    //      for fixed k reads one contiguous 128B row.
    __shared__ u64 sW1[32][18];
    __shared__ u64 sW2[32][16];
    __shared__ u64 sW3[16];
    __shared__ u64 sb1[32];
    __shared__ u64 sb2[16];

    const int tid = threadIdx.x;
    for (int i = tid; i < 32 * 17; i += BLOCK) {
        int k = i / 17, ii = i % 17;
        float w = W1[ii * 32 + k];
        sW1[k][ii] = pack2(w, w);
    }
    for (int i = tid; i < 32 * 16; i += BLOCK) {
        float w = W2[i];
        sW2[i / 16][i % 16] = pack2(w, w);
    }
    if (tid < 32) { float v = b1[tid]; sb1[tid] = pack2(v, v); }
    if (tid < 16) {
        float w = W3[tid]; sW3[tid] = pack2(w, w);
        float v = b2[tid]; sb2[tid] = pack2(v, v);
    }
    __syncthreads();

    const int t  = blockIdx.x * BLOCK + tid;
    const int e0 = t;
    const int e1 = t + NTHREADS;
    const int e2 = t + 2 * NTHREADS;
    const int e3 = t + 3 * NTHREADS;

    // ---- Quantum feature: <Z0> = prod_{i=1..6} cos(x_q[i] + qp[i]) ----
    // (CNOT-ring GF(2): qubit-0 value = parity(b1..b6); each factor
    //  cos^2(h)-sin^2(h) = cos(2h) = cos(x+w); qubit 0's angle cancels.)
    float q0 = 1.0f, q1 = 1.0f, q2 = 1.0f, q3 = 1.0f;
#pragma unroll
    for (int i = 1; i < 7; i++) {
        float w = __ldg(qp + i);
        q0 *= __cosf(__ldg(xq + e0 * 7 + i) + w);
        q1 *= __cosf(__ldg(xq + e1 * 7 + i) + w);
        q2 *= __cosf(__ldg(xq + e2 * 7 + i) + w);
        q3 *= __cosf(__ldg(xq + e3 * 7 + i) + w);
    }

    // ---- Inputs: feature 0 = q_out, features 1..16 = x_c ----
    u64 inA[17], inB[17];
    inA[0] = pack2(q0, q1);
    inB[0] = pack2(q2, q3);
    {
        const float4* c0 = (const float4*)(xc + (long)e0 * 16);
        const float4* c1 = (const float4*)(xc + (long)e1 * 16);
        const float4* c2 = (const float4*)(xc + (long)e2 * 16);
        const float4* c3 = (const float4*)(xc + (long)e3 * 16);
#pragma unroll
        for (int q = 0; q < 4; q++) {
            float4 a = __ldg(c0 + q);
            float4 b = __ldg(c1 + q);
            float4 c = __ldg(c2 + q);
            float4 d = __ldg(c3 + q);
            inA[1 + q * 4 + 0] = pack2(a.x, b.x);
            inA[1 + q * 4 + 1] = pack2(a.y, b.y);
            inA[1 + q * 4 + 2] = pack2(a.z, b.z);
            inA[1 + q * 4 + 3] = pack2(a.w, b.w);
            inB[1 + q * 4 + 0] = pack2(c.x, d.x);
            inB[1 + q * 4 + 1] = pack2(c.y, d.y);
            inB[1 + q * 4 + 2] = pack2(c.z, d.z);
            inB[1 + q * 4 + 3] = pack2(c.w, d.w);
        }
    }

    // ---- Fused layers 1+2: h2 += W2[k,:] * relu(W1[:,k].in + b1[k]) ----
    u64 hA[16], hB[16];
#pragma unroll
    for (int j = 0; j < 16; j++) { hA[j] = sb2[j]; hB[j] = sb2[j]; }

#pragma unroll 4
    for (int k = 0; k < 32; k++) {
        u64 a = sb1[k];
        u64 b = a;
        const ulonglong2* r1 = (const ulonglong2*)&sW1[k][0];
#pragma unroll
        for (int i = 0; i < 8; i++) {
            ulonglong2 w = r1[i];
            a = fma2(inA[2 * i + 0], w.x, a);
            a = fma2(inA[2 * i + 1], w.y, a);
            b = fma2(inB[2 * i + 0], w.x, b);
            b = fma2(inB[2 * i + 1], w.y, b);
        }
        u64 wl = sW1[k][16];
        a = fma2(inA[16], wl, a);
        b = fma2(inB[16], wl, b);
        a = relu2(a);
        b = relu2(b);
        const ulonglong2* r2 = (const ulonglong2*)&sW2[k][0];
#pragma unroll
        for (int j = 0; j < 8; j++) {
            ulonglong2 w = r2[j];
            hA[2 * j + 0] = fma2(a, w.x, hA[2 * j + 0]);
            hA[2 * j + 1] = fma2(a, w.y, hA[2 * j + 1]);
            hB[2 * j + 0] = fma2(b, w.x, hB[2 * j + 0]);
            hB[2 * j + 1] = fma2(b, w.y, hB[2 * j + 1]);
        }
    }

    // ---- Layer 3: 16 -> 1 ----
    float bb = __ldg(b3);
    u64 accA = pack2(bb, bb);
    u64 accB = accA;
#pragma unroll
    for (int j = 0; j < 16; j++) {
        accA = fma2(relu2(hA[j]), sW3[j], accA);
        accB = fma2(relu2(hB[j]), sW3[j], accB);
    }

    float o0, o1, o2, o3;
    unpack2(accA, o0, o1);
    unpack2(accB, o2, o3);
    out[e0] = o0;
    out[e1] = o1;
    out[e2] = o2;
    out[e3] = o3;
}

extern "C" void kernel_launch(void* const* d_in, const int* in_sizes, int n_in,
                              void* d_out, int out_size)
{
    const float* xq = (const float*)d_in[0];
    const float* xc = (const float*)d_in[1];
    const float* qp = (const float*)d_in[2];
    const float* W1 = (const float*)d_in[3];
    const float* b1 = (const float*)d_in[4];
    const float* W2 = (const float*)d_in[5];
    const float* b2 = (const float*)d_in[6];
    const float* W3 = (const float*)d_in[7];
    const float* b3 = (const float*)d_in[8];
    float* out = (float*)d_out;

    hybridq_kernel<<<NTHREADS / BLOCK, BLOCK>>>(xq, xc, qp, W1, b1, W2, b2, W3, b3, out);
}